// round 3
// baseline (speedup 1.0000x reference)
#include <cuda_runtime.h>

#define NQ   12
#define DIM  4096
#define TPB  256

__device__ __forceinline__ int pad_idx(int i) { return i + (i >> 4); }

// One gate pass: 4 qubits (bits BASE..BASE+3 of the linear index) processed in
// registers. PERM fuses the CNOT-chain permutation into the load (gather from
// idx ^ (idx>>1)). STORE=false leaves results in registers for readout.
template<int BASE, bool PERM, bool STORE>
__device__ __forceinline__ void gate_pass(
    float* __restrict__ sRe, float* __restrict__ sIm,
    const float* __restrict__ gC,  const float* __restrict__ gS,
    const float* __restrict__ gEsr, const float* __restrict__ gEsi,
    const float* __restrict__ gEcr, const float* __restrict__ gEci,
    int t, float ar[16], float ai[16])
{
    __syncthreads();  // previous pass stores visible
#pragma unroll
    for (int j = 0; j < 16; ++j) {
        int idx;
        if (BASE == 0)      idx = (t << 4) | j;
        else if (BASE == 4) idx = ((t & 0xF0) << 4) | (j << 4) | (t & 15);
        else                idx = (j << 8) | t;
        int src = PERM ? (idx ^ (idx >> 1)) : idx;
        ar[j] = sRe[pad_idx(src)];
        ai[j] = sIm[pad_idx(src)];
    }
    if (PERM) __syncthreads();  // gather crosses thread-ownership; drain reads before writes

#pragma unroll
    for (int k = 0; k < 4; ++k) {
        const int q = 11 - (BASE + k);
        const float c   = gC[q],   s   = gS[q];
        const float esr = gEsr[q], esi = gEsi[q];
        const float ecr = gEcr[q], eci = gEci[q];
#pragma unroll
        for (int m = 0; m < 8; ++m) {
            const int j0 = ((m >> k) << (k + 1)) | (m & ((1 << k) - 1));
            const int j1 = j0 | (1 << k);
            const float a0r = ar[j0], a0i = ai[j0];
            const float a1r = ar[j1], a1i = ai[j1];
            // out0 = c*a0 - s*a1   (c, s real)
            ar[j0] = c * a0r - s * a1r;
            ai[j0] = c * a0i - s * a1i;
            // out1 = e^{i phi} * (s*a0 + c*a1) = es*a0 + ec*a1 (complex coeffs)
            ar[j1] = esr * a0r - esi * a0i + ecr * a1r - eci * a1i;
            ai[j1] = esr * a0i + esi * a0r + ecr * a1i + eci * a1r;
        }
    }

    if (STORE) {
#pragma unroll
        for (int j = 0; j < 16; ++j) {
            int idx;
            if (BASE == 0)      idx = (t << 4) | j;
            else if (BASE == 4) idx = ((t & 0xF0) << 4) | (j << 4) | (t & 15);
            else                idx = (j << 8) | t;
            sRe[pad_idx(idx)] = ar[j];
            sIm[pad_idx(idx)] = ai[j];
        }
    }
}

__global__ __launch_bounds__(TPB)
void vqc_kernel(const float* __restrict__ inputs,
                const float* __restrict__ thetas,
                float* __restrict__ out)
{
    __shared__ float sRe[DIM + (DIM >> 4)];
    __shared__ float sIm[DIM + (DIM >> 4)];
    __shared__ float gC[2][NQ], gS[2][NQ];
    __shared__ float gEsr[2][NQ], gEsi[2][NQ], gEcr[2][NQ], gEci[2][NQ];
    __shared__ float vR[2 * NQ], vI[2 * NQ];
    __shared__ float red[NQ];

    const int t   = threadIdx.x;
    const int blk = blockIdx.x;

    // ---- per-block gate tables (12 threads) --------------------------------
    if (t < NQ) {
        red[t] = 0.0f;
        const int q = t;
        const float x = inputs[blk * NQ + q];
        float pxr, pxi;
        sincospif(x, &pxi, &pxr);                 // e^{i pi x}

        // layer 0 fused with encoding: v = Z^t1 * Y^t0 * (1, e^{i pi x})/sqrt2
        {
            const float t0 = thetas[q * 2 + 0];
            const float t1 = thetas[q * 2 + 1];
            float s, c;  sincospif(0.5f * t0, &s, &c);
            float epi, epr; sincospif(t1, &epi, &epr);
            const float R = 0.70710678118654752f;
            vR[2 * q + 0] = (c - s * pxr) * R;
            vI[2 * q + 0] = (-s * pxi) * R;
            const float wr = s + c * pxr, wi = c * pxi;
            vR[2 * q + 1] = (epr * wr - epi * wi) * R;
            vI[2 * q + 1] = (epr * wi + epi * wr) * R;
        }
        // layers 1, 2
#pragma unroll
        for (int l = 1; l <= 2; ++l) {
            const float t0 = thetas[l * 24 + q * 2 + 0];
            const float t1 = thetas[l * 24 + q * 2 + 1];
            float s, c;  sincospif(0.5f * t0, &s, &c);
            float epi, epr; sincospif(t1, &epi, &epr);
            gC[l - 1][q] = c;        gS[l - 1][q] = s;
            gEsr[l - 1][q] = epr * s; gEsi[l - 1][q] = epi * s;
            gEcr[l - 1][q] = epr * c; gEci[l - 1][q] = epi * c;
        }
    }
    __syncthreads();

    float ar[16], ai[16];

    // ---- init: product state = encoding + layer-0 1q gates ----------------
    {
        // bits 4..11 of index come from t -> qubits 7..0
        float cr = 1.0f, ci = 0.0f;
#pragma unroll
        for (int b = 4; b < 12; ++b) {
            const int q   = 11 - b;
            const int bit = (t >> (b - 4)) & 1;
            const float wr = vR[2 * q + bit], wi = vI[2 * q + bit];
            const float nr = cr * wr - ci * wi;
            const float ni = cr * wi + ci * wr;
            cr = nr; ci = ni;
        }
        // bits 0..3 -> qubits 11..8, built by doubling
        ar[0] = vR[2 * 11 + 0]; ai[0] = vI[2 * 11 + 0];
        ar[1] = vR[2 * 11 + 1]; ai[1] = vI[2 * 11 + 1];
#pragma unroll
        for (int b = 1; b < 4; ++b) {
            const int q  = 11 - b;
            const int sz = 1 << b;
            const float w0r = vR[2 * q + 0], w0i = vI[2 * q + 0];
            const float w1r = vR[2 * q + 1], w1i = vI[2 * q + 1];
#pragma unroll
            for (int j = 0; j < 8; ++j) {        // only j < sz active
                if (j < sz) {
                    const int jr = sz - 1 - j;   // descending so in-place is safe
                    const float lr = ar[jr], li = ai[jr];
                    ar[jr + sz] = lr * w1r - li * w1i;
                    ai[jr + sz] = lr * w1i + li * w1r;
                    ar[jr]      = lr * w0r - li * w0i;
                    ai[jr]      = lr * w0i + li * w0r;
                }
            }
        }
#pragma unroll
        for (int j = 0; j < 16; ++j) {
            const float nr = ar[j] * cr - ai[j] * ci;
            const float ni = ar[j] * ci + ai[j] * cr;
            const int idx = (t << 4) | j;        // pass-0 layout
            sRe[pad_idx(idx)] = nr;
            sIm[pad_idx(idx)] = ni;
        }
    }

    // ---- layer 1 (after CNOT chain #1, fused into pass-0 gather) ----------
    gate_pass<0, true,  true >(sRe, sIm, gC[0], gS[0], gEsr[0], gEsi[0], gEcr[0], gEci[0], t, ar, ai);
    gate_pass<4, false, true >(sRe, sIm, gC[0], gS[0], gEsr[0], gEsi[0], gEcr[0], gEci[0], t, ar, ai);
    gate_pass<8, false, true >(sRe, sIm, gC[0], gS[0], gEsr[0], gEsi[0], gEcr[0], gEci[0], t, ar, ai);

    // ---- layer 2 (after CNOT chain #2) -------------------------------------
    gate_pass<0, true,  true >(sRe, sIm, gC[1], gS[1], gEsr[1], gEsi[1], gEcr[1], gEci[1], t, ar, ai);
    gate_pass<4, false, true >(sRe, sIm, gC[1], gS[1], gEsr[1], gEsi[1], gEcr[1], gEci[1], t, ar, ai);
    gate_pass<8, false, false>(sRe, sIm, gC[1], gS[1], gEsr[1], gEsi[1], gEcr[1], gEci[1], t, ar, ai);

    // ---- readout from registers: idx = (j<<8) | t --------------------------
    float T = 0.0f, b8 = 0.0f, b9 = 0.0f, b10 = 0.0f, b11 = 0.0f;
#pragma unroll
    for (int j = 0; j < 16; ++j) {
        const float p = ar[j] * ar[j] + ai[j] * ai[j];
        T += p;
        b8  += (j & 1) ? -p : p;
        b9  += (j & 2) ? -p : p;
        b10 += (j & 4) ? -p : p;
        b11 += (j & 8) ? -p : p;
    }
    float val[NQ];
#pragma unroll
    for (int b = 0; b < 8; ++b) val[b] = ((t >> b) & 1) ? -T : T;
    val[8] = b8; val[9] = b9; val[10] = b10; val[11] = b11;

#pragma unroll
    for (int b = 0; b < NQ; ++b) {
#pragma unroll
        for (int off = 16; off > 0; off >>= 1)
            val[b] += __shfl_xor_sync(0xffffffffu, val[b], off);
    }
    if ((t & 31) == 0) {
#pragma unroll
        for (int b = 0; b < NQ; ++b) atomicAdd(&red[b], val[b]);
    }
    __syncthreads();

    // <Z_q> : qubit q lives at bit 11-q
    if (t < NQ) out[blk * NQ + t] = red[11 - t];
}

extern "C" void kernel_launch(void* const* d_in, const int* in_sizes, int n_in,
                              void* d_out, int out_size)
{
    const float* inputs = (const float*)d_in[0];
    const float* thetas = (const float*)d_in[1];
    float* out = (float*)d_out;
    const int batch = in_sizes[0] / NQ;
    vqc_kernel<<<batch, TPB>>>(inputs, thetas, out);
}

// round 4
// speedup vs baseline: 1.0115x; 1.0115x over previous
#include <cuda_runtime.h>

#define NQ   12
#define DIM  4096
#define TPB  256

__device__ __forceinline__ int pad_idx(int i) { return i + (i >> 4); }

// One gate pass: 4 qubits (bits BASE..BASE+3 of the linear index) processed in
// registers. PERM fuses the CNOT-chain permutation into the load (gather from
// idx ^ (idx>>1)). STORE=false leaves results in registers for readout.
template<int BASE, bool PERM, bool STORE>
__device__ __forceinline__ void gate_pass(
    float* __restrict__ sRe, float* __restrict__ sIm,
    const float* __restrict__ gC,  const float* __restrict__ gS,
    const float* __restrict__ gEsr, const float* __restrict__ gEsi,
    const float* __restrict__ gEcr, const float* __restrict__ gEci,
    int t, float ar[16], float ai[16])
{
    __syncthreads();  // previous pass stores visible
#pragma unroll
    for (int j = 0; j < 16; ++j) {
        int idx;
        if (BASE == 0)      idx = (t << 4) | j;
        else if (BASE == 4) idx = ((t & 0xF0) << 4) | (j << 4) | (t & 15);
        else                idx = (j << 8) | t;
        int src = PERM ? (idx ^ (idx >> 1)) : idx;
        ar[j] = sRe[pad_idx(src)];
        ai[j] = sIm[pad_idx(src)];
    }
    if (PERM) __syncthreads();  // gather crosses thread-ownership; drain reads before writes

#pragma unroll
    for (int k = 0; k < 4; ++k) {
        const int q = 11 - (BASE + k);
        const float c   = gC[q],   s   = gS[q];
        const float esr = gEsr[q], esi = gEsi[q];
        const float ecr = gEcr[q], eci = gEci[q];
#pragma unroll
        for (int m = 0; m < 8; ++m) {
            const int j0 = ((m >> k) << (k + 1)) | (m & ((1 << k) - 1));
            const int j1 = j0 | (1 << k);
            const float a0r = ar[j0], a0i = ai[j0];
            const float a1r = ar[j1], a1i = ai[j1];
            // out0 = c*a0 - s*a1   (c, s real)
            ar[j0] = c * a0r - s * a1r;
            ai[j0] = c * a0i - s * a1i;
            // out1 = e^{i phi} * (s*a0 + c*a1) = es*a0 + ec*a1 (complex coeffs)
            ar[j1] = esr * a0r - esi * a0i + ecr * a1r - eci * a1i;
            ai[j1] = esr * a0i + esi * a0r + ecr * a1i + eci * a1r;
        }
    }

    if (STORE) {
#pragma unroll
        for (int j = 0; j < 16; ++j) {
            int idx;
            if (BASE == 0)      idx = (t << 4) | j;
            else if (BASE == 4) idx = ((t & 0xF0) << 4) | (j << 4) | (t & 15);
            else                idx = (j << 8) | t;
            sRe[pad_idx(idx)] = ar[j];
            sIm[pad_idx(idx)] = ai[j];
        }
    }
}

__global__ __launch_bounds__(TPB)
void vqc_kernel(const float* __restrict__ inputs,
                const float* __restrict__ thetas,
                float* __restrict__ out)
{
    __shared__ float sRe[DIM + (DIM >> 4)];
    __shared__ float sIm[DIM + (DIM >> 4)];
    __shared__ float gC[2][NQ], gS[2][NQ];
    __shared__ float gEsr[2][NQ], gEsi[2][NQ], gEcr[2][NQ], gEci[2][NQ];
    __shared__ float vR[2 * NQ], vI[2 * NQ];
    __shared__ float red[NQ];

    const int t   = threadIdx.x;
    const int blk = blockIdx.x;

    // ---- per-block gate tables (12 threads) --------------------------------
    if (t < NQ) {
        red[t] = 0.0f;
        const int q = t;
        const float x = inputs[blk * NQ + q];
        float pxr, pxi;
        sincospif(x, &pxi, &pxr);                 // e^{i pi x}

        // layer 0 fused with encoding: v = Z^t1 * Y^t0 * (1, e^{i pi x})/sqrt2
        {
            const float t0 = thetas[q * 2 + 0];
            const float t1 = thetas[q * 2 + 1];
            float s, c;  sincospif(0.5f * t0, &s, &c);
            float epi, epr; sincospif(t1, &epi, &epr);
            const float R = 0.70710678118654752f;
            vR[2 * q + 0] = (c - s * pxr) * R;
            vI[2 * q + 0] = (-s * pxi) * R;
            const float wr = s + c * pxr, wi = c * pxi;
            vR[2 * q + 1] = (epr * wr - epi * wi) * R;
            vI[2 * q + 1] = (epr * wi + epi * wr) * R;
        }
        // layers 1, 2
#pragma unroll
        for (int l = 1; l <= 2; ++l) {
            const float t0 = thetas[l * 24 + q * 2 + 0];
            const float t1 = thetas[l * 24 + q * 2 + 1];
            float s, c;  sincospif(0.5f * t0, &s, &c);
            float epi, epr; sincospif(t1, &epi, &epr);
            gC[l - 1][q] = c;        gS[l - 1][q] = s;
            gEsr[l - 1][q] = epr * s; gEsi[l - 1][q] = epi * s;
            gEcr[l - 1][q] = epr * c; gEci[l - 1][q] = epi * c;
        }
    }
    __syncthreads();

    float ar[16], ai[16];

    // ---- init: product state = encoding + layer-0 1q gates ----------------
    {
        // bits 4..11 of index come from t -> qubits 7..0
        float cr = 1.0f, ci = 0.0f;
#pragma unroll
        for (int b = 4; b < 12; ++b) {
            const int q   = 11 - b;
            const int bit = (t >> (b - 4)) & 1;
            const float wr = vR[2 * q + bit], wi = vI[2 * q + bit];
            const float nr = cr * wr - ci * wi;
            const float ni = cr * wi + ci * wr;
            cr = nr; ci = ni;
        }
        // bits 0..3 -> qubits 11..8, built by doubling
        ar[0] = vR[2 * 11 + 0]; ai[0] = vI[2 * 11 + 0];
        ar[1] = vR[2 * 11 + 1]; ai[1] = vI[2 * 11 + 1];
#pragma unroll
        for (int b = 1; b < 4; ++b) {
            const int q  = 11 - b;
            const int sz = 1 << b;
            const float w0r = vR[2 * q + 0], w0i = vI[2 * q + 0];
            const float w1r = vR[2 * q + 1], w1i = vI[2 * q + 1];
#pragma unroll
            for (int j = 0; j < 8; ++j) {        // only j < sz active
                if (j < sz) {
                    const int jr = sz - 1 - j;   // descending so in-place is safe
                    const float lr = ar[jr], li = ai[jr];
                    ar[jr + sz] = lr * w1r - li * w1i;
                    ai[jr + sz] = lr * w1i + li * w1r;
                    ar[jr]      = lr * w0r - li * w0i;
                    ai[jr]      = lr * w0i + li * w0r;
                }
            }
        }
#pragma unroll
        for (int j = 0; j < 16; ++j) {
            const float nr = ar[j] * cr - ai[j] * ci;
            const float ni = ar[j] * ci + ai[j] * cr;
            const int idx = (t << 4) | j;        // pass-0 layout
            sRe[pad_idx(idx)] = nr;
            sIm[pad_idx(idx)] = ni;
        }
    }

    // ---- layer 1 (after CNOT chain #1, fused into pass-0 gather) ----------
    gate_pass<0, true,  true >(sRe, sIm, gC[0], gS[0], gEsr[0], gEsi[0], gEcr[0], gEci[0], t, ar, ai);
    gate_pass<4, false, true >(sRe, sIm, gC[0], gS[0], gEsr[0], gEsi[0], gEcr[0], gEci[0], t, ar, ai);
    gate_pass<8, false, true >(sRe, sIm, gC[0], gS[0], gEsr[0], gEsi[0], gEcr[0], gEci[0], t, ar, ai);

    // ---- layer 2 (after CNOT chain #2) -------------------------------------
    gate_pass<0, true,  true >(sRe, sIm, gC[1], gS[1], gEsr[1], gEsi[1], gEcr[1], gEci[1], t, ar, ai);
    gate_pass<4, false, true >(sRe, sIm, gC[1], gS[1], gEsr[1], gEsi[1], gEcr[1], gEci[1], t, ar, ai);
    gate_pass<8, false, false>(sRe, sIm, gC[1], gS[1], gEsr[1], gEsi[1], gEcr[1], gEci[1], t, ar, ai);

    // ---- readout from registers: idx = (j<<8) | t --------------------------
    float T = 0.0f, b8 = 0.0f, b9 = 0.0f, b10 = 0.0f, b11 = 0.0f;
#pragma unroll
    for (int j = 0; j < 16; ++j) {
        const float p = ar[j] * ar[j] + ai[j] * ai[j];
        T += p;
        b8  += (j & 1) ? -p : p;
        b9  += (j & 2) ? -p : p;
        b10 += (j & 4) ? -p : p;
        b11 += (j & 8) ? -p : p;
    }
    float val[NQ];
#pragma unroll
    for (int b = 0; b < 8; ++b) val[b] = ((t >> b) & 1) ? -T : T;
    val[8] = b8; val[9] = b9; val[10] = b10; val[11] = b11;

#pragma unroll
    for (int b = 0; b < NQ; ++b) {
#pragma unroll
        for (int off = 16; off > 0; off >>= 1)
            val[b] += __shfl_xor_sync(0xffffffffu, val[b], off);
    }
    if ((t & 31) == 0) {
#pragma unroll
        for (int b = 0; b < NQ; ++b) atomicAdd(&red[b], val[b]);
    }
    __syncthreads();

    // <Z_q> : qubit q lives at bit 11-q
    if (t < NQ) out[blk * NQ + t] = red[11 - t];
}

extern "C" void kernel_launch(void* const* d_in, const int* in_sizes, int n_in,
                              void* d_out, int out_size)
{
    const float* inputs = (const float*)d_in[0];
    const float* thetas = (const float*)d_in[1];
    float* out = (float*)d_out;
    const int batch = in_sizes[0] / NQ;
    vqc_kernel<<<batch, TPB>>>(inputs, thetas, out);
}

// round 5
// speedup vs baseline: 1.0129x; 1.0014x over previous
#include <cuda_runtime.h>

#define NQ   12
#define DIM  4096
#define TPB  256

__device__ __forceinline__ int pad_idx(int i) { return i + (i >> 4); }

// One gate pass: 4 qubits (bits BASE..BASE+3 of the linear index) processed in
// registers. PERM fuses the CNOT-chain permutation into the load (gather from
// idx ^ (idx>>1)). STORE=false leaves results in registers for readout.
template<int BASE, bool PERM, bool STORE>
__device__ __forceinline__ void gate_pass(
    float* __restrict__ sRe, float* __restrict__ sIm,
    const float* __restrict__ gC,  const float* __restrict__ gS,
    const float* __restrict__ gEsr, const float* __restrict__ gEsi,
    const float* __restrict__ gEcr, const float* __restrict__ gEci,
    int t, float ar[16], float ai[16])
{
    __syncthreads();  // previous pass stores visible
#pragma unroll
    for (int j = 0; j < 16; ++j) {
        int idx;
        if (BASE == 0)      idx = (t << 4) | j;
        else if (BASE == 4) idx = ((t & 0xF0) << 4) | (j << 4) | (t & 15);
        else                idx = (j << 8) | t;
        int src = PERM ? (idx ^ (idx >> 1)) : idx;
        ar[j] = sRe[pad_idx(src)];
        ai[j] = sIm[pad_idx(src)];
    }
    if (PERM) __syncthreads();  // gather crosses thread-ownership; drain reads before writes

#pragma unroll
    for (int k = 0; k < 4; ++k) {
        const int q = 11 - (BASE + k);
        const float c   = gC[q],   s   = gS[q];
        const float esr = gEsr[q], esi = gEsi[q];
        const float ecr = gEcr[q], eci = gEci[q];
#pragma unroll
        for (int m = 0; m < 8; ++m) {
            const int j0 = ((m >> k) << (k + 1)) | (m & ((1 << k) - 1));
            const int j1 = j0 | (1 << k);
            const float a0r = ar[j0], a0i = ai[j0];
            const float a1r = ar[j1], a1i = ai[j1];
            // out0 = c*a0 - s*a1   (c, s real)
            ar[j0] = c * a0r - s * a1r;
            ai[j0] = c * a0i - s * a1i;
            // out1 = e^{i phi} * (s*a0 + c*a1) = es*a0 + ec*a1 (complex coeffs)
            ar[j1] = esr * a0r - esi * a0i + ecr * a1r - eci * a1i;
            ai[j1] = esr * a0i + esi * a0r + ecr * a1i + eci * a1r;
        }
    }

    if (STORE) {
#pragma unroll
        for (int j = 0; j < 16; ++j) {
            int idx;
            if (BASE == 0)      idx = (t << 4) | j;
            else if (BASE == 4) idx = ((t & 0xF0) << 4) | (j << 4) | (t & 15);
            else                idx = (j << 8) | t;
            sRe[pad_idx(idx)] = ar[j];
            sIm[pad_idx(idx)] = ai[j];
        }
    }
}

__global__ __launch_bounds__(TPB)
void vqc_kernel(const float* __restrict__ inputs,
                const float* __restrict__ thetas,
                float* __restrict__ out)
{
    __shared__ float sRe[DIM + (DIM >> 4)];
    __shared__ float sIm[DIM + (DIM >> 4)];
    __shared__ float gC[2][NQ], gS[2][NQ];
    __shared__ float gEsr[2][NQ], gEsi[2][NQ], gEcr[2][NQ], gEci[2][NQ];
    __shared__ float vR[2 * NQ], vI[2 * NQ];
    __shared__ float red[NQ];

    const int t   = threadIdx.x;
    const int blk = blockIdx.x;

    // ---- per-block gate tables (12 threads) --------------------------------
    if (t < NQ) {
        red[t] = 0.0f;
        const int q = t;
        const float x = inputs[blk * NQ + q];
        float pxr, pxi;
        sincospif(x, &pxi, &pxr);                 // e^{i pi x}

        // layer 0 fused with encoding: v = Z^t1 * Y^t0 * (1, e^{i pi x})/sqrt2
        {
            const float t0 = thetas[q * 2 + 0];
            const float t1 = thetas[q * 2 + 1];
            float s, c;  sincospif(0.5f * t0, &s, &c);
            float epi, epr; sincospif(t1, &epi, &epr);
            const float R = 0.70710678118654752f;
            vR[2 * q + 0] = (c - s * pxr) * R;
            vI[2 * q + 0] = (-s * pxi) * R;
            const float wr = s + c * pxr, wi = c * pxi;
            vR[2 * q + 1] = (epr * wr - epi * wi) * R;
            vI[2 * q + 1] = (epr * wi + epi * wr) * R;
        }
        // layers 1, 2
#pragma unroll
        for (int l = 1; l <= 2; ++l) {
            const float t0 = thetas[l * 24 + q * 2 + 0];
            const float t1 = thetas[l * 24 + q * 2 + 1];
            float s, c;  sincospif(0.5f * t0, &s, &c);
            float epi, epr; sincospif(t1, &epi, &epr);
            gC[l - 1][q] = c;        gS[l - 1][q] = s;
            gEsr[l - 1][q] = epr * s; gEsi[l - 1][q] = epi * s;
            gEcr[l - 1][q] = epr * c; gEci[l - 1][q] = epi * c;
        }
    }
    __syncthreads();

    float ar[16], ai[16];

    // ---- init: product state = encoding + layer-0 1q gates ----------------
    {
        // bits 4..11 of index come from t -> qubits 7..0
        float cr = 1.0f, ci = 0.0f;
#pragma unroll
        for (int b = 4; b < 12; ++b) {
            const int q   = 11 - b;
            const int bit = (t >> (b - 4)) & 1;
            const float wr = vR[2 * q + bit], wi = vI[2 * q + bit];
            const float nr = cr * wr - ci * wi;
            const float ni = cr * wi + ci * wr;
            cr = nr; ci = ni;
        }
        // bits 0..3 -> qubits 11..8, built by doubling
        ar[0] = vR[2 * 11 + 0]; ai[0] = vI[2 * 11 + 0];
        ar[1] = vR[2 * 11 + 1]; ai[1] = vI[2 * 11 + 1];
#pragma unroll
        for (int b = 1; b < 4; ++b) {
            const int q  = 11 - b;
            const int sz = 1 << b;
            const float w0r = vR[2 * q + 0], w0i = vI[2 * q + 0];
            const float w1r = vR[2 * q + 1], w1i = vI[2 * q + 1];
#pragma unroll
            for (int j = 0; j < 8; ++j) {        // only j < sz active
                if (j < sz) {
                    const int jr = sz - 1 - j;   // descending so in-place is safe
                    const float lr = ar[jr], li = ai[jr];
                    ar[jr + sz] = lr * w1r - li * w1i;
                    ai[jr + sz] = lr * w1i + li * w1r;
                    ar[jr]      = lr * w0r - li * w0i;
                    ai[jr]      = lr * w0i + li * w0r;
                }
            }
        }
#pragma unroll
        for (int j = 0; j < 16; ++j) {
            const float nr = ar[j] * cr - ai[j] * ci;
            const float ni = ar[j] * ci + ai[j] * cr;
            const int idx = (t << 4) | j;        // pass-0 layout
            sRe[pad_idx(idx)] = nr;
            sIm[pad_idx(idx)] = ni;
        }
    }

    // ---- layer 1 (after CNOT chain #1, fused into pass-0 gather) ----------
    gate_pass<0, true,  true >(sRe, sIm, gC[0], gS[0], gEsr[0], gEsi[0], gEcr[0], gEci[0], t, ar, ai);
    gate_pass<4, false, true >(sRe, sIm, gC[0], gS[0], gEsr[0], gEsi[0], gEcr[0], gEci[0], t, ar, ai);
    gate_pass<8, false, true >(sRe, sIm, gC[0], gS[0], gEsr[0], gEsi[0], gEcr[0], gEci[0], t, ar, ai);

    // ---- layer 2 (after CNOT chain #2) -------------------------------------
    gate_pass<0, true,  true >(sRe, sIm, gC[1], gS[1], gEsr[1], gEsi[1], gEcr[1], gEci[1], t, ar, ai);
    gate_pass<4, false, true >(sRe, sIm, gC[1], gS[1], gEsr[1], gEsi[1], gEcr[1], gEci[1], t, ar, ai);
    gate_pass<8, false, false>(sRe, sIm, gC[1], gS[1], gEsr[1], gEsi[1], gEcr[1], gEci[1], t, ar, ai);

    // ---- readout from registers: idx = (j<<8) | t --------------------------
    float T = 0.0f, b8 = 0.0f, b9 = 0.0f, b10 = 0.0f, b11 = 0.0f;
#pragma unroll
    for (int j = 0; j < 16; ++j) {
        const float p = ar[j] * ar[j] + ai[j] * ai[j];
        T += p;
        b8  += (j & 1) ? -p : p;
        b9  += (j & 2) ? -p : p;
        b10 += (j & 4) ? -p : p;
        b11 += (j & 8) ? -p : p;
    }
    float val[NQ];
#pragma unroll
    for (int b = 0; b < 8; ++b) val[b] = ((t >> b) & 1) ? -T : T;
    val[8] = b8; val[9] = b9; val[10] = b10; val[11] = b11;

#pragma unroll
    for (int b = 0; b < NQ; ++b) {
#pragma unroll
        for (int off = 16; off > 0; off >>= 1)
            val[b] += __shfl_xor_sync(0xffffffffu, val[b], off);
    }
    if ((t & 31) == 0) {
#pragma unroll
        for (int b = 0; b < NQ; ++b) atomicAdd(&red[b], val[b]);
    }
    __syncthreads();

    // <Z_q> : qubit q lives at bit 11-q
    if (t < NQ) out[blk * NQ + t] = red[11 - t];
}

extern "C" void kernel_launch(void* const* d_in, const int* in_sizes, int n_in,
                              void* d_out, int out_size)
{
    const float* inputs = (const float*)d_in[0];
    const float* thetas = (const float*)d_in[1];
    float* out = (float*)d_out;
    const int batch = in_sizes[0] / NQ;
    vqc_kernel<<<batch, TPB>>>(inputs, thetas, out);
}

// round 6
// speedup vs baseline: 1.0492x; 1.0358x over previous
#include <cuda_runtime.h>

#define NQ   12
#define DIM  4096
#define TPB  256

__device__ __forceinline__ int pad_idx(int i) { return i + (i >> 4); }

// One gate pass: 4 qubits (bits BASE..BASE+3 of the linear index) processed in
// registers. PERM fuses the CNOT-chain permutation into the load (gather from
// idx ^ (idx>>1)). STORE=false leaves results in registers for readout.
template<int BASE, bool PERM, bool STORE>
__device__ __forceinline__ void gate_pass(
    float* __restrict__ sRe, float* __restrict__ sIm,
    const float* __restrict__ gC,  const float* __restrict__ gS,
    const float* __restrict__ gEsr, const float* __restrict__ gEsi,
    const float* __restrict__ gEcr, const float* __restrict__ gEci,
    int t, float ar[16], float ai[16])
{
    __syncthreads();  // previous pass stores visible
#pragma unroll
    for (int j = 0; j < 16; ++j) {
        int idx;
        if (BASE == 0)      idx = (t << 4) | j;
        else if (BASE == 4) idx = ((t & 0xF0) << 4) | (j << 4) | (t & 15);
        else                idx = (j << 8) | t;
        int src = PERM ? (idx ^ (idx >> 1)) : idx;
        ar[j] = sRe[pad_idx(src)];
        ai[j] = sIm[pad_idx(src)];
    }
    if (PERM) __syncthreads();  // gather crosses thread-ownership; drain reads before writes

#pragma unroll
    for (int k = 0; k < 4; ++k) {
        const int q = 11 - (BASE + k);
        const float c   = gC[q],   s   = gS[q];
        const float esr = gEsr[q], esi = gEsi[q];
        const float ecr = gEcr[q], eci = gEci[q];
#pragma unroll
        for (int m = 0; m < 8; ++m) {
            const int j0 = ((m >> k) << (k + 1)) | (m & ((1 << k) - 1));
            const int j1 = j0 | (1 << k);
            const float a0r = ar[j0], a0i = ai[j0];
            const float a1r = ar[j1], a1i = ai[j1];
            // out0 = c*a0 - s*a1   (c, s real)
            ar[j0] = c * a0r - s * a1r;
            ai[j0] = c * a0i - s * a1i;
            // out1 = e^{i phi} * (s*a0 + c*a1) = es*a0 + ec*a1 (complex coeffs)
            ar[j1] = esr * a0r - esi * a0i + ecr * a1r - eci * a1i;
            ai[j1] = esr * a0i + esi * a0r + ecr * a1i + eci * a1r;
        }
    }

    if (STORE) {
#pragma unroll
        for (int j = 0; j < 16; ++j) {
            int idx;
            if (BASE == 0)      idx = (t << 4) | j;
            else if (BASE == 4) idx = ((t & 0xF0) << 4) | (j << 4) | (t & 15);
            else                idx = (j << 8) | t;
            sRe[pad_idx(idx)] = ar[j];
            sIm[pad_idx(idx)] = ai[j];
        }
    }
}

__global__ __launch_bounds__(TPB)
void vqc_kernel(const float* __restrict__ inputs,
                const float* __restrict__ thetas,
                float* __restrict__ out)
{
    __shared__ float sRe[DIM + (DIM >> 4)];
    __shared__ float sIm[DIM + (DIM >> 4)];
    __shared__ float gC[2][NQ], gS[2][NQ];
    __shared__ float gEsr[2][NQ], gEsi[2][NQ], gEcr[2][NQ], gEci[2][NQ];
    __shared__ float vR[2 * NQ], vI[2 * NQ];
    __shared__ float red[NQ];

    const int t   = threadIdx.x;
    const int blk = blockIdx.x;

    // ---- per-block gate tables (12 threads) --------------------------------
    if (t < NQ) {
        red[t] = 0.0f;
        const int q = t;
        const float x = inputs[blk * NQ + q];
        float pxr, pxi;
        sincospif(x, &pxi, &pxr);                 // e^{i pi x}

        // layer 0 fused with encoding: v = Z^t1 * Y^t0 * (1, e^{i pi x})/sqrt2
        {
            const float t0 = thetas[q * 2 + 0];
            const float t1 = thetas[q * 2 + 1];
            float s, c;  sincospif(0.5f * t0, &s, &c);
            float epi, epr; sincospif(t1, &epi, &epr);
            const float R = 0.70710678118654752f;
            vR[2 * q + 0] = (c - s * pxr) * R;
            vI[2 * q + 0] = (-s * pxi) * R;
            const float wr = s + c * pxr, wi = c * pxi;
            vR[2 * q + 1] = (epr * wr - epi * wi) * R;
            vI[2 * q + 1] = (epr * wi + epi * wr) * R;
        }
        // layers 1, 2
#pragma unroll
        for (int l = 1; l <= 2; ++l) {
            const float t0 = thetas[l * 24 + q * 2 + 0];
            const float t1 = thetas[l * 24 + q * 2 + 1];
            float s, c;  sincospif(0.5f * t0, &s, &c);
            float epi, epr; sincospif(t1, &epi, &epr);
            gC[l - 1][q] = c;        gS[l - 1][q] = s;
            gEsr[l - 1][q] = epr * s; gEsi[l - 1][q] = epi * s;
            gEcr[l - 1][q] = epr * c; gEci[l - 1][q] = epi * c;
        }
    }
    __syncthreads();

    float ar[16], ai[16];

    // ---- init: product state = encoding + layer-0 1q gates ----------------
    {
        // bits 4..11 of index come from t -> qubits 7..0
        float cr = 1.0f, ci = 0.0f;
#pragma unroll
        for (int b = 4; b < 12; ++b) {
            const int q   = 11 - b;
            const int bit = (t >> (b - 4)) & 1;
            const float wr = vR[2 * q + bit], wi = vI[2 * q + bit];
            const float nr = cr * wr - ci * wi;
            const float ni = cr * wi + ci * wr;
            cr = nr; ci = ni;
        }
        // bits 0..3 -> qubits 11..8, built by doubling
        ar[0] = vR[2 * 11 + 0]; ai[0] = vI[2 * 11 + 0];
        ar[1] = vR[2 * 11 + 1]; ai[1] = vI[2 * 11 + 1];
#pragma unroll
        for (int b = 1; b < 4; ++b) {
            const int q  = 11 - b;
            const int sz = 1 << b;
            const float w0r = vR[2 * q + 0], w0i = vI[2 * q + 0];
            const float w1r = vR[2 * q + 1], w1i = vI[2 * q + 1];
#pragma unroll
            for (int j = 0; j < 8; ++j) {        // only j < sz active
                if (j < sz) {
                    const int jr = sz - 1 - j;   // descending so in-place is safe
                    const float lr = ar[jr], li = ai[jr];
                    ar[jr + sz] = lr * w1r - li * w1i;
                    ai[jr + sz] = lr * w1i + li * w1r;
                    ar[jr]      = lr * w0r - li * w0i;
                    ai[jr]      = lr * w0i + li * w0r;
                }
            }
        }
#pragma unroll
        for (int j = 0; j < 16; ++j) {
            const float nr = ar[j] * cr - ai[j] * ci;
            const float ni = ar[j] * ci + ai[j] * cr;
            const int idx = (t << 4) | j;        // pass-0 layout
            sRe[pad_idx(idx)] = nr;
            sIm[pad_idx(idx)] = ni;
        }
    }

    // ---- layer 1 (after CNOT chain #1, fused into pass-0 gather) ----------
    gate_pass<0, true,  true >(sRe, sIm, gC[0], gS[0], gEsr[0], gEsi[0], gEcr[0], gEci[0], t, ar, ai);
    gate_pass<4, false, true >(sRe, sIm, gC[0], gS[0], gEsr[0], gEsi[0], gEcr[0], gEci[0], t, ar, ai);
    gate_pass<8, false, true >(sRe, sIm, gC[0], gS[0], gEsr[0], gEsi[0], gEcr[0], gEci[0], t, ar, ai);

    // ---- layer 2 (after CNOT chain #2) -------------------------------------
    gate_pass<0, true,  true >(sRe, sIm, gC[1], gS[1], gEsr[1], gEsi[1], gEcr[1], gEci[1], t, ar, ai);
    gate_pass<4, false, true >(sRe, sIm, gC[1], gS[1], gEsr[1], gEsi[1], gEcr[1], gEci[1], t, ar, ai);
    gate_pass<8, false, false>(sRe, sIm, gC[1], gS[1], gEsr[1], gEsi[1], gEcr[1], gEci[1], t, ar, ai);

    // ---- readout from registers: idx = (j<<8) | t --------------------------
    float T = 0.0f, b8 = 0.0f, b9 = 0.0f, b10 = 0.0f, b11 = 0.0f;
#pragma unroll
    for (int j = 0; j < 16; ++j) {
        const float p = ar[j] * ar[j] + ai[j] * ai[j];
        T += p;
        b8  += (j & 1) ? -p : p;
        b9  += (j & 2) ? -p : p;
        b10 += (j & 4) ? -p : p;
        b11 += (j & 8) ? -p : p;
    }
    float val[NQ];
#pragma unroll
    for (int b = 0; b < 8; ++b) val[b] = ((t >> b) & 1) ? -T : T;
    val[8] = b8; val[9] = b9; val[10] = b10; val[11] = b11;

#pragma unroll
    for (int b = 0; b < NQ; ++b) {
#pragma unroll
        for (int off = 16; off > 0; off >>= 1)
            val[b] += __shfl_xor_sync(0xffffffffu, val[b], off);
    }
    if ((t & 31) == 0) {
#pragma unroll
        for (int b = 0; b < NQ; ++b) atomicAdd(&red[b], val[b]);
    }
    __syncthreads();

    // <Z_q> : qubit q lives at bit 11-q
    if (t < NQ) out[blk * NQ + t] = red[11 - t];
}

extern "C" void kernel_launch(void* const* d_in, const int* in_sizes, int n_in,
                              void* d_out, int out_size)
{
    const float* inputs = (const float*)d_in[0];
    const float* thetas = (const float*)d_in[1];
    float* out = (float*)d_out;
    const int batch = in_sizes[0] / NQ;
    vqc_kernel<<<batch, TPB>>>(inputs, thetas, out);
}